// round 13
// baseline (speedup 1.0000x reference)
#include <cuda_runtime.h>

#define HH 1024
#define WW 1536
#define NN (HH*WW)

// CCL tiles
#define BTW 64
#define BTH 64
#define NVB ((WW/BTW - 1) * HH)   // vertical boundary pixels: 23*1024
#define NHB ((HH/BTH - 1) * WW)   // horizontal boundary pixels: 15*1536

// ---------------- device scratch (no allocation allowed) ----------------
// pooled zero-init region: [0,NN)=y1 ; [NN,2NN)=y2 ; [2NN,3NN+1)=cnt
static __device__ int g_pool[3 * NN + 1];
static __device__ int g_dst[NN];
static __device__ unsigned char g_mask[NN];
static __device__ int g_par[NN];
static __device__ int g_labi[NN];

// ---------------- kernels ----------------

// dst_ids + first scatter fused; 4 px/thread (float4 plane loads)
__global__ void k_dst_scat1(const float* __restrict__ yh, const float* __restrict__ df,
                            int* __restrict__ dst, int* __restrict__ y1) {
    int q = blockIdx.x * blockDim.x + threadIdx.x;
    if (q >= NN / 4) return;
    int i = q * 4;
    float4 vx = *(const float4*)(df + i);
    float4 vy = *(const float4*)(df + NN + i);
    float4 vh = *(const float4*)(yh + i);
    int r = i / WW;                       // WW%4==0 -> same row for all 4
    int c = i - r * WW;
    int4 d;
    float dxs[4] = {vx.x, vx.y, vx.z, vx.w};
    float dys[4] = {vy.x, vy.y, vy.z, vy.w};
    int   ds[4];
#pragma unroll
    for (int k = 0; k < 4; k++) {
        float dx = dxs[k], dy = dys[k];
        float l2  = __fadd_rn(__fmul_rn(dx, dx), __fmul_rn(dy, dy));
        float len = __fsqrt_rn(l2);
        float den = __fadd_rn(len, 1e-19f);
        float ux  = __fdiv_rn(dx, den);
        float uy  = __fdiv_rn(dy, den);
        float dfc = fminf(fmaxf(len, 3.0f), 6.0f);
        float px = __fadd_rn((float)r, __fmul_rn(ux, dfc));
        float py = __fadd_rn((float)(c + k), __fmul_rn(uy, dfc));
        px = fminf(fmaxf(px, 0.0f), (float)(HH - 1));
        py = fminf(fmaxf(py, 0.0f), (float)(WW - 1));
        ds[k] = __float2int_rn(px) * WW + __float2int_rn(py);  // ties-to-even
    }
    d.x = ds[0]; d.y = ds[1]; d.z = ds[2]; d.w = ds[3];
    *(int4*)(dst + i) = d;
    if (vh.x > 0.5f) atomicAdd(&y1[d.x], 1);
    if (vh.y > 0.5f) atomicAdd(&y1[d.y], 1);
    if (vh.z > 0.5f) atomicAdd(&y1[d.z], 1);
    if (vh.w > 0.5f) atomicAdd(&y1[d.w], 1);
}

// y2[dst[i]] += y1[i]; 4 px/thread
__global__ void k_scat2(const int* __restrict__ dst, const int* __restrict__ y1,
                        int* __restrict__ y2) {
    int q = blockIdx.x * blockDim.x + threadIdx.x;
    if (q >= NN / 4) return;
    int i = q * 4;
    int4 v = *(const int4*)(y1 + i);
    if (v.x | v.y | v.z | v.w) {
        int4 d = *(const int4*)(dst + i);
        if (v.x) atomicAdd(&y2[d.x], v.x);
        if (v.y) atomicAdd(&y2[d.y], v.y);
        if (v.z) atomicAdd(&y2[d.z], v.z);
        if (v.w) atomicAdd(&y2[d.w], v.w);
    }
}

// ---- fused avgpool5(count_include_pad=False) + threshold + cross-erosion ----
#define TW 32
#define TH 8
__global__ void k_pool_erode(const int* __restrict__ y2,
                             unsigned char* __restrict__ mask) {
    __shared__ int y2s[14][38];            // rows gr0-3..gr0+10, cols gc0-3..gc0+34
    __shared__ int css[10][38];            // row k ~ image row gr0-1+k
    __shared__ unsigned char m0s[10][36];  // (k,j) ~ (gr0-1+k, gc0-1+j); OOB = 1

    int tx = threadIdx.x, ty = threadIdx.y;
    int tid = ty * TW + tx;
    int gr0 = blockIdx.y * TH;
    int gc0 = blockIdx.x * TW;

    for (int k = tid; k < 14 * 38; k += TW * TH) {
        int rr = k / 38, cc = k % 38;
        int gr = gr0 - 3 + rr, gc = gc0 - 3 + cc;
        y2s[rr][cc] = (gr >= 0 && gr < HH && gc >= 0 && gc < WW) ? y2[gr * WW + gc] : 0;
    }
    __syncthreads();

    for (int k = tid; k < 10 * 38; k += TW * TH) {
        int rr = k / 38, cc = k % 38;
        css[rr][cc] = y2s[rr][cc] + y2s[rr + 1][cc] + y2s[rr + 2][cc]
                    + y2s[rr + 3][cc] + y2s[rr + 4][cc];
    }
    __syncthreads();

    for (int k = tid; k < 10 * 36; k += TW * TH) {
        int rr = k / 36, jj = k % 36;
        int r = gr0 - 1 + rr, c = gc0 - 1 + jj;
        unsigned char m;
        if (r < 0 || r >= HH || c < 0 || c >= WW) {
            m = 1;                                   // pad = foreground
        } else {
            int s = css[rr][jj] + css[rr][jj + 1] + css[rr][jj + 2]
                  + css[rr][jj + 3] + css[rr][jj + 4];
            int rin = min(r + 2, HH - 1) - max(r - 2, 0) + 1;
            int cin = min(c + 2, WW - 1) - max(c - 2, 0) + 1;
            m = (unsigned char)(2 * s >= rin * cin);
        }
        m0s[rr][jj] = m;
    }
    __syncthreads();

    int r = gr0 + ty, c = gc0 + tx;
    unsigned char m = m0s[ty + 1][tx + 1] & m0s[ty][tx + 1] & m0s[ty + 2][tx + 1]
                    & m0s[ty + 1][tx] & m0s[ty + 1][tx + 2];
    mask[r * WW + c] = m;
}

// ---- shared-memory union-find (local CCL) ----
__device__ __forceinline__ int lfind(int* lp, int i) {
    int p = lp[i];
    while (true) {
        int pp = lp[p];
        if (pp == p) return p;
        lp[i] = pp;           // halving (monotone parents -> safe)
        i = p; p = pp;
    }
}

__device__ void lunion(int* lp, int a, int b) {
    while (true) {
        a = lfind(lp, a);
        b = lfind(lp, b);
        if (a == b) return;
        int hi = max(a, b);
        int lo = min(a, b);
        int old = atomicCAS(&lp[lo], lo, hi);
        if (old == lo) return;
        a = hi; b = old;
    }
}

// per-tile CCL in smem; flatten to global parent array (depth <= 1 per tile)
__global__ void k_ccl_local(const unsigned char* __restrict__ mask, int* __restrict__ par) {
    __shared__ int lp[BTW * BTH];              // 16 KB
    __shared__ unsigned char lm[BTW * BTH];    // 4 KB

    int tid = threadIdx.x;                     // 256 threads
    int R0 = blockIdx.y * BTH, C0 = blockIdx.x * BTW;

    // load mask tile, 16B per thread iteration
    for (int k = tid; k < BTW * BTH / 16; k += 256) {
        int lr = k >> 2, lc = (k & 3) * 16;
        *(int4*)&lm[lr * BTW + lc] = *(const int4*)&mask[(R0 + lr) * WW + C0 + lc];
    }
    for (int k = tid; k < BTW * BTH; k += 256) lp[k] = k;
    __syncthreads();

    // intra-tile unions: E, S, SW, SE
    for (int k = tid; k < BTW * BTH; k += 256) {
        if (!lm[k]) continue;
        int lr = k >> 6, lc = k & 63;
        if (lc < 63 && lm[k + 1])  lunion(lp, k, k + 1);
        if (lr < 63) {
            if (lm[k + BTW])            lunion(lp, k, k + BTW);
            if (lc > 0  && lm[k + BTW - 1]) lunion(lp, k, k + BTW - 1);
            if (lc < 63 && lm[k + BTW + 1]) lunion(lp, k, k + BTW + 1);
        }
    }
    __syncthreads();

    // flatten to global ids (local root = local max -> g() monotone -> par[gi] >= gi)
    for (int k = tid; k < BTW * BTH; k += 256) {
        int lr = k >> 6, lc = k & 63;
        int gi = (R0 + lr) * WW + C0 + lc;
        if (lm[k]) {
            int rt = k, p = lp[rt];
            while (p != rt) { rt = p; p = lp[rt]; }
            par[gi] = (R0 + (rt >> 6)) * WW + C0 + (rt & 63);
        } else {
            par[gi] = gi;
        }
    }
}

// global find with path halving (parents strictly increasing -> no ABA)
__device__ __forceinline__ int uf_find(int* __restrict__ par, int i) {
    int p = par[i];
    while (true) {
        int pp = par[p];
        if (p == pp) return p;
        par[i] = pp;
        i = p; p = pp;
    }
}

__device__ void uf_union(int* __restrict__ par, int a, int b) {
    while (true) {
        a = uf_find(par, a);
        b = uf_find(par, b);
        if (a == b) return;
        int hi = max(a, b);
        int lo = min(a, b);
        int old = atomicCAS(&par[lo], lo, hi);
        if (old == lo) return;
        a = hi; b = old;
    }
}

// cross-tile edges only (~47k threads)
__global__ void k_ccl_merge(const unsigned char* __restrict__ mask, int* __restrict__ par) {
    int t = blockIdx.x * blockDim.x + threadIdx.x;
    if (t < NVB) {
        // vertical boundary: line v, row r, col = last col of tile
        int v = t / HH, r = t - v * HH;
        int c = (v + 1) * BTW - 1;
        int i = r * WW + c;
        unsigned char mi = mask[i], mE = mask[i + 1];
        if (mi && mE) uf_union(par, i, i + 1);
        if (r < HH - 1) {
            if (mi && mask[i + WW + 1]) uf_union(par, i, i + WW + 1);       // SE
            if (mE && mask[i + WW])     uf_union(par, i + 1, i + WW);       // SW of (r,c+1)
        }
    } else {
        t -= NVB;
        if (t >= NHB) return;
        // horizontal boundary: line h, row = last row of tile, col c
        int h = t / WW, c = t - h * WW;
        int r = (h + 1) * BTH - 1;                  // r <= 959 < HH-1
        int i = r * WW + c;
        if (!mask[i]) return;
        if (mask[i + WW])              uf_union(par, i, i + WW);
        if (c > 0      && mask[i + WW - 1]) uf_union(par, i, i + WW - 1);
        if (c < WW - 1 && mask[i + WW + 1]) uf_union(par, i, i + WW + 1);
    }
}

// inst = label(dst^8(i)) * fore ; warp-aggregated per-label histogram
__global__ void k_labi(const float* __restrict__ yh, const int* __restrict__ dst,
                       const unsigned char* __restrict__ mask, int* __restrict__ par,
                       int* __restrict__ labi, int* __restrict__ cnt) {
    int i = blockIdx.x * blockDim.x + threadIdx.x;   // grid exact: NN % 256 == 0
    int la = 0;
    if (yh[i] > 0.5f) {
        int j = i;
#pragma unroll
        for (int h = 0; h < 8; h++) j = dst[j];
        if (mask[j]) la = uf_find(par, j) + 1;
    }
    labi[i] = la;
    unsigned peers = __match_any_sync(0xffffffffu, la);
    int lane = threadIdx.x & 31;
    if (la > 0 && (__ffs(peers) - 1) == lane)
        atomicAdd(&cnt[la], __popc(peers));
}

// keep components with size > 256; value = label (segment_max(L)==L exactly)
__global__ void k_final(const int* __restrict__ labi, const int* __restrict__ cnt,
                        float* __restrict__ out) {
    int q = blockIdx.x * blockDim.x + threadIdx.x;
    if (q >= NN / 4) return;
    int i = q * 4;
    int4 la = *(const int4*)(labi + i);
    float4 o;
    o.x = (la.x > 0 && cnt[la.x] > 256) ? (float)la.x : 0.0f;
    o.y = (la.y > 0 && cnt[la.y] > 256) ? (float)la.y : 0.0f;
    o.z = (la.z > 0 && cnt[la.z] > 256) ? (float)la.z : 0.0f;
    o.w = (la.w > 0 && cnt[la.w] > 256) ? (float)la.w : 0.0f;
    *(float4*)(out + i) = o;
}

// ---------------- launcher ----------------
extern "C" void kernel_launch(void* const* d_in, const int* in_sizes, int n_in,
                              void* d_out, int out_size) {
    const float* y_hat;
    const float* df;
    if (in_sizes[0] == NN) { y_hat = (const float*)d_in[0]; df = (const float*)d_in[1]; }
    else                   { df = (const float*)d_in[0]; y_hat = (const float*)d_in[1]; }
    float* out = (float*)d_out;

    void *ppool, *pdst, *pmask, *ppar, *plabi;
    cudaGetSymbolAddress(&ppool, g_pool);
    cudaGetSymbolAddress(&pdst, g_dst);
    cudaGetSymbolAddress(&pmask, g_mask);
    cudaGetSymbolAddress(&ppar, g_par);
    cudaGetSymbolAddress(&plabi, g_labi);

    int* y1  = (int*)ppool;
    int* y2  = y1 + NN;
    int* cnt = y1 + 2 * NN;

    cudaMemsetAsync(ppool, 0, (size_t)(3 * NN + 1) * 4, 0);

    const int B = 256;
    const int G  = (NN + B - 1) / B;
    const int G4 = (NN / 4 + B - 1) / B;

    k_dst_scat1<<<G4, B>>>(y_hat, df, (int*)pdst, y1);
    k_scat2<<<G4, B>>>((const int*)pdst, y1, y2);
    {
        dim3 blk(TW, TH);
        dim3 grd(WW / TW, HH / TH);
        k_pool_erode<<<grd, blk>>>(y2, (unsigned char*)pmask);
    }
    {
        dim3 grd(WW / BTW, HH / BTH);          // 24 x 16 tiles
        k_ccl_local<<<grd, 256>>>((const unsigned char*)pmask, (int*)ppar);
    }
    k_ccl_merge<<<(NVB + NHB + B - 1) / B, B>>>((const unsigned char*)pmask, (int*)ppar);
    k_labi<<<G, B>>>(y_hat, (const int*)pdst, (const unsigned char*)pmask,
                     (int*)ppar, (int*)plabi, cnt);
    k_final<<<G4, B>>>((const int*)plabi, cnt, out);
}

// round 15
// speedup vs baseline: 1.3513x; 1.3513x over previous
#include <cuda_runtime.h>

#define HH 1024
#define WW 1536
#define NN (HH*WW)

// 2x2 block grid
#define BW2 768              // WW/2
#define BH2 512              // HH/2
#define NB (BW2*BH2)         // 393216 blocks

// ---------------- device scratch (no allocation allowed) ----------------
// pooled zero-init region: [0,NN)=y1 ; [NN,2NN)=y2 ; [2NN,3NN+1)=cnt ; then maxlab[NB]
static __device__ int g_pool[3 * NN + 1 + NB];
static __device__ int g_dst[NN];
static __device__ unsigned char g_bpat[NB];   // 4-bit fg pattern per 2x2 block
static __device__ int g_bpar[NB];             // block union-find parents
static __device__ int g_labi[NN];

// block pattern bits: 0=TL(r0,c0) 1=TR(r0,c1) 2=BL(r1,c0) 3=BR(r1,c1)

// ---------------- kernels ----------------

// dst_ids + first scatter fused; 4 px/thread (float4 plane loads)
__global__ void k_dst_scat1(const float* __restrict__ yh, const float* __restrict__ df,
                            int* __restrict__ dst, int* __restrict__ y1) {
    int q = blockIdx.x * blockDim.x + threadIdx.x;
    if (q >= NN / 4) return;
    int i = q * 4;
    float4 vx = *(const float4*)(df + i);
    float4 vy = *(const float4*)(df + NN + i);
    float4 vh = *(const float4*)(yh + i);
    int r = i / WW;                       // WW%4==0 -> same row for all 4
    int c = i - r * WW;
    int4 d;
    float dxs[4] = {vx.x, vx.y, vx.z, vx.w};
    float dys[4] = {vy.x, vy.y, vy.z, vy.w};
    int   ds[4];
#pragma unroll
    for (int k = 0; k < 4; k++) {
        float dx = dxs[k], dy = dys[k];
        float l2  = __fadd_rn(__fmul_rn(dx, dx), __fmul_rn(dy, dy));
        float len = __fsqrt_rn(l2);
        float den = __fadd_rn(len, 1e-19f);
        float ux  = __fdiv_rn(dx, den);
        float uy  = __fdiv_rn(dy, den);
        float dfc = fminf(fmaxf(len, 3.0f), 6.0f);
        float px = __fadd_rn((float)r, __fmul_rn(ux, dfc));
        float py = __fadd_rn((float)(c + k), __fmul_rn(uy, dfc));
        px = fminf(fmaxf(px, 0.0f), (float)(HH - 1));
        py = fminf(fmaxf(py, 0.0f), (float)(WW - 1));
        ds[k] = __float2int_rn(px) * WW + __float2int_rn(py);  // ties-to-even
    }
    d.x = ds[0]; d.y = ds[1]; d.z = ds[2]; d.w = ds[3];
    *(int4*)(dst + i) = d;
    if (vh.x > 0.5f) atomicAdd(&y1[d.x], 1);
    if (vh.y > 0.5f) atomicAdd(&y1[d.y], 1);
    if (vh.z > 0.5f) atomicAdd(&y1[d.z], 1);
    if (vh.w > 0.5f) atomicAdd(&y1[d.w], 1);
}

// y2[dst[i]] += y1[i]; 4 px/thread
__global__ void k_scat2(const int* __restrict__ dst, const int* __restrict__ y1,
                        int* __restrict__ y2) {
    int q = blockIdx.x * blockDim.x + threadIdx.x;
    if (q >= NN / 4) return;
    int i = q * 4;
    int4 v = *(const int4*)(y1 + i);
    if (v.x | v.y | v.z | v.w) {
        int4 d = *(const int4*)(dst + i);
        if (v.x) atomicAdd(&y2[d.x], v.x);
        if (v.y) atomicAdd(&y2[d.y], v.y);
        if (v.z) atomicAdd(&y2[d.z], v.z);
        if (v.w) atomicAdd(&y2[d.w], v.w);
    }
}

// ---- fused avgpool5(count_include_pad=False) + threshold + cross-erosion
//      + 2x2 block pattern packing + block parent init ----
#define TW 32
#define TH 8
__global__ void k_pool_erode(const int* __restrict__ y2,
                             unsigned char* __restrict__ bpat,
                             int* __restrict__ bpar) {
    __shared__ int y2s[14][38];            // rows gr0-3..gr0+10, cols gc0-3..gc0+34
    __shared__ int css[10][38];            // row k ~ image row gr0-1+k
    __shared__ unsigned char m0s[10][36];  // (k,j) ~ (gr0-1+k, gc0-1+j); OOB = 1
    __shared__ unsigned char mes[TH][TW];  // eroded mask for the tile

    int tx = threadIdx.x, ty = threadIdx.y;
    int tid = ty * TW + tx;
    int gr0 = blockIdx.y * TH;
    int gc0 = blockIdx.x * TW;

    for (int k = tid; k < 14 * 38; k += TW * TH) {
        int rr = k / 38, cc = k % 38;
        int gr = gr0 - 3 + rr, gc = gc0 - 3 + cc;
        y2s[rr][cc] = (gr >= 0 && gr < HH && gc >= 0 && gc < WW) ? y2[gr * WW + gc] : 0;
    }
    __syncthreads();

    for (int k = tid; k < 10 * 38; k += TW * TH) {
        int rr = k / 38, cc = k % 38;
        css[rr][cc] = y2s[rr][cc] + y2s[rr + 1][cc] + y2s[rr + 2][cc]
                    + y2s[rr + 3][cc] + y2s[rr + 4][cc];
    }
    __syncthreads();

    for (int k = tid; k < 10 * 36; k += TW * TH) {
        int rr = k / 36, jj = k % 36;
        int r = gr0 - 1 + rr, c = gc0 - 1 + jj;
        unsigned char m;
        if (r < 0 || r >= HH || c < 0 || c >= WW) {
            m = 1;                                   // pad = foreground
        } else {
            int s = css[rr][jj] + css[rr][jj + 1] + css[rr][jj + 2]
                  + css[rr][jj + 3] + css[rr][jj + 4];
            int rin = min(r + 2, HH - 1) - max(r - 2, 0) + 1;
            int cin = min(c + 2, WW - 1) - max(c - 2, 0) + 1;
            m = (unsigned char)(2 * s >= rin * cin);
        }
        m0s[rr][jj] = m;
    }
    __syncthreads();

    mes[ty][tx] = m0s[ty + 1][tx + 1] & m0s[ty][tx + 1] & m0s[ty + 2][tx + 1]
                & m0s[ty + 1][tx] & m0s[ty + 1][tx + 2];
    __syncthreads();

    // pack 2x2 blocks: tile has 16x4 blocks; threads 0..63
    if (tid < (TW / 2) * (TH / 2)) {
        int tx2 = tid & (TW / 2 - 1);          // 0..15
        int ty2 = tid >> 4;                    // 0..3
        unsigned char p = (unsigned char)(mes[ty2 * 2][tx2 * 2]
                        | (mes[ty2 * 2][tx2 * 2 + 1] << 1)
                        | (mes[ty2 * 2 + 1][tx2 * 2] << 2)
                        | (mes[ty2 * 2 + 1][tx2 * 2 + 1] << 3));
        int gb = ((gr0 >> 1) + ty2) * BW2 + (gc0 >> 1) + tx2;
        bpat[gb] = p;
        bpar[gb] = gb;
    }
}

// find with path halving (parents strictly increasing -> no ABA)
__device__ __forceinline__ int uf_find(int* __restrict__ par, int i) {
    int p = par[i];
    while (true) {
        int pp = par[p];
        if (p == pp) return p;
        par[i] = pp;
        i = p; p = pp;
    }
}

// lock-free union: hook smaller root under larger root
__device__ void uf_union(int* __restrict__ par, int a, int b) {
    while (true) {
        a = uf_find(par, a);
        b = uf_find(par, b);
        if (a == b) return;
        int hi = max(a, b);
        int lo = min(a, b);
        int old = atomicCAS(&par[lo], lo, hi);
        if (old == lo) return;
        a = hi; b = old;
    }
}

// block-level unions: E, S, SW, SE neighbors via pattern bit tests
// bits: 1=TL 2=TR 4=BL 8=BR ; right col=0xA left col=0x5 bottom=0xC top=0x3
__global__ void k_bunion(const unsigned char* __restrict__ bpat, int* __restrict__ bpar) {
    int b = blockIdx.x * blockDim.x + threadIdx.x;
    if (b >= NB) return;
    unsigned p = bpat[b];
    if (!p) return;
    int br = b / BW2, bc = b - br * BW2;
    if (bc < BW2 - 1 && (p & 0xA) && (bpat[b + 1] & 0x5)) uf_union(bpar, b, b + 1);
    if (br < BH2 - 1) {
        if ((p & 0xC) && (bpat[b + BW2] & 0x3))              uf_union(bpar, b, b + BW2);
        if (bc > 0 && (p & 0x4) && (bpat[b + BW2 - 1] & 0x2)) uf_union(bpar, b, b + BW2 - 1);
        if (bc < BW2 - 1 && (p & 0x8) && (bpat[b + BW2 + 1] & 0x1)) uf_union(bpar, b, b + BW2 + 1);
    }
}

// per-component max pixel index via atomicMax on the root
__global__ void k_bmax(const unsigned char* __restrict__ bpat, int* __restrict__ bpar,
                       int* __restrict__ maxlab) {
    int b = blockIdx.x * blockDim.x + threadIdx.x;
    if (b >= NB) return;
    unsigned p = bpat[b];
    if (!p) return;
    int br = b / BW2, bc = b - br * BW2;
    int r0 = br * 2, c0 = bc * 2;
    int m;
    if      (p & 8) m = (r0 + 1) * WW + c0 + 1;
    else if (p & 4) m = (r0 + 1) * WW + c0;
    else if (p & 2) m = r0 * WW + c0 + 1;
    else            m = r0 * WW + c0;
    int rt = uf_find(bpar, b);
    atomicMax(&maxlab[rt], m);
}

// inst = label(dst^8(i)) * fore ; warp-aggregated per-label histogram
__global__ void k_labi(const float* __restrict__ yh, const int* __restrict__ dst,
                       const unsigned char* __restrict__ bpat, int* __restrict__ bpar,
                       const int* __restrict__ maxlab,
                       int* __restrict__ labi, int* __restrict__ cnt) {
    int i = blockIdx.x * blockDim.x + threadIdx.x;   // grid exact: NN % 256 == 0
    int la = 0;
    if (yh[i] > 0.5f) {
        int j = i;
#pragma unroll
        for (int h = 0; h < 8; h++) j = dst[j];
        int r = j / WW, c = j - r * WW;
        int bj = (r >> 1) * BW2 + (c >> 1);
        int bit = ((r & 1) << 1) | (c & 1);
        if ((bpat[bj] >> bit) & 1)
            la = maxlab[uf_find(bpar, bj)] + 1;
    }
    labi[i] = la;
    unsigned peers = __match_any_sync(0xffffffffu, la);
    int lane = threadIdx.x & 31;
    if (la > 0 && (__ffs(peers) - 1) == lane)
        atomicAdd(&cnt[la], __popc(peers));
}

// keep components with size > 256; value = label (segment_max(L)==L exactly)
__global__ void k_final(const int* __restrict__ labi, const int* __restrict__ cnt,
                        float* __restrict__ out) {
    int q = blockIdx.x * blockDim.x + threadIdx.x;
    if (q >= NN / 4) return;
    int i = q * 4;
    int4 la = *(const int4*)(labi + i);
    float4 o;
    o.x = (la.x > 0 && cnt[la.x] > 256) ? (float)la.x : 0.0f;
    o.y = (la.y > 0 && cnt[la.y] > 256) ? (float)la.y : 0.0f;
    o.z = (la.z > 0 && cnt[la.z] > 256) ? (float)la.z : 0.0f;
    o.w = (la.w > 0 && cnt[la.w] > 256) ? (float)la.w : 0.0f;
    *(float4*)(out + i) = o;
}

// ---------------- launcher ----------------
extern "C" void kernel_launch(void* const* d_in, const int* in_sizes, int n_in,
                              void* d_out, int out_size) {
    const float* y_hat;
    const float* df;
    if (in_sizes[0] == NN) { y_hat = (const float*)d_in[0]; df = (const float*)d_in[1]; }
    else                   { df = (const float*)d_in[0]; y_hat = (const float*)d_in[1]; }
    float* out = (float*)d_out;

    void *ppool, *pdst, *pbpat, *pbpar, *plabi;
    cudaGetSymbolAddress(&ppool, g_pool);
    cudaGetSymbolAddress(&pdst, g_dst);
    cudaGetSymbolAddress(&pbpat, g_bpat);
    cudaGetSymbolAddress(&pbpar, g_bpar);
    cudaGetSymbolAddress(&plabi, g_labi);

    int* y1     = (int*)ppool;
    int* y2     = y1 + NN;
    int* cnt    = y1 + 2 * NN;          // NN+1 ints
    int* maxlab = y1 + 3 * NN + 1;      // NB ints

    cudaMemsetAsync(ppool, 0, (size_t)(3 * NN + 1 + NB) * 4, 0);

    const int B = 256;
    const int G  = (NN + B - 1) / B;
    const int G4 = (NN / 4 + B - 1) / B;
    const int GB = (NB + B - 1) / B;

    k_dst_scat1<<<G4, B>>>(y_hat, df, (int*)pdst, y1);
    k_scat2<<<G4, B>>>((const int*)pdst, y1, y2);
    {
        dim3 blk(TW, TH);
        dim3 grd(WW / TW, HH / TH);
        k_pool_erode<<<grd, blk>>>(y2, (unsigned char*)pbpat, (int*)pbpar);
    }
    k_bunion<<<GB, B>>>((const unsigned char*)pbpat, (int*)pbpar);
    k_bmax<<<GB, B>>>((const unsigned char*)pbpat, (int*)pbpar, maxlab);
    k_labi<<<G, B>>>(y_hat, (const int*)pdst, (const unsigned char*)pbpat,
                     (int*)pbpar, maxlab, (int*)plabi, cnt);
    k_final<<<G4, B>>>((const int*)plabi, cnt, out);
}